// round 9
// baseline (speedup 1.0000x reference)
#include <cuda_runtime.h>

#define NN 100000
#define EE 3200000
#define F_IN 100
#define HID 16
#define NC 18

// Scratch (static device arrays — zero-initialized at module load)
__device__ __align__(128) float g_hs[NN * HID];    // dinv*[h@W] per node (conv input msg)
__device__ __align__(128) float g_hs2[NN * HID];   // double buffer for conv2
__device__ __align__(128) float g_dinv[NN];
__device__ __align__(128) int   g_deg[NN];         // INVARIANT: zero at call entry
__device__ __align__(128) int   g_rowstart[NN + 1];
__device__ __align__(128) int   g_cursor[NN];
__device__ __align__(128) int   g_col[EE];         // CSR (by dst) column = src
__device__ __align__(128) unsigned long long g_pk[128];  // lookback: (val<<2)|state

#define SCAN_B 1024
#define SCAN_G 98   // 98*1024 = 100352 >= NN

// ---------------------------------------------------------------------------
// K1: in-degree count (int4-vectorized). Also zeroes lookback flags.
__global__ void k_deg(const int* __restrict__ dst, int E) {
    if (blockIdx.x == 0 && threadIdx.x < 128) g_pk[threadIdx.x] = 0ULL;
    int t = blockIdx.x * blockDim.x + threadIdx.x;
    int e = t * 4;
    if (e + 3 < E) {
        int4 d = *(const int4*)(dst + e);
        atomicAdd(&g_deg[d.x], 1);
        atomicAdd(&g_deg[d.y], 1);
        atomicAdd(&g_deg[d.z], 1);
        atomicAdd(&g_deg[d.w], 1);
    } else {
        for (int k = e; k < E; k++) atomicAdd(&g_deg[dst[k]], 1);
    }
}

// ---------------------------------------------------------------------------
// K2 (fused): blocks 0..97 = single-pass scan (decoupled lookback);
//             blocks 98..  = node0 (h0 = relu(x@W1+b1); hs = dinv*(h0@Wc0)).
// Both roles only read g_deg (complete after K1). Neither writes it.
__global__ __launch_bounds__(1024) void k_scan_node0(
        const float* __restrict__ x,  const float* __restrict__ W1,
        const float* __restrict__ b1, const float* __restrict__ Wc0, int E) {
    int tid = threadIdx.x;

    if (blockIdx.x < SCAN_G) {
        // ---------------- scan role ----------------
        __shared__ int s[SCAN_B];
        __shared__ int sprefix;
        int bid = blockIdx.x;
        int i = bid * SCAN_B + tid;
        int v = (i < NN) ? g_deg[i] : 0;
        s[tid] = v;
        __syncthreads();
        for (int off = 1; off < SCAN_B; off <<= 1) {
            int t2 = (tid >= off) ? s[tid - off] : 0;
            __syncthreads();
            s[tid] += t2;
            __syncthreads();
        }
        int total = s[SCAN_B - 1];
        if (tid == 0) {
            if (bid == 0) {
                atomicExch(&g_pk[0], (((unsigned long long)(unsigned)total) << 2) | 2ULL);
                sprefix = 0;
            } else {
                atomicExch(&g_pk[bid], (((unsigned long long)(unsigned)total) << 2) | 1ULL);
                int pref = 0, j = bid - 1;
                while (true) {
                    unsigned long long q;
                    do { q = atomicAdd(&g_pk[j], 0ULL); } while ((q & 3ULL) == 0ULL);
                    pref += (int)(unsigned)(q >> 2);
                    if ((q & 3ULL) == 2ULL) break;
                    j--;
                }
                atomicExch(&g_pk[bid],
                    (((unsigned long long)(unsigned)(total + pref)) << 2) | 2ULL);
                sprefix = pref;
            }
        }
        __syncthreads();
        if (i < NN) {
            int r = s[tid] - v + sprefix;   // exclusive global prefix
            g_rowstart[i] = r;
            g_cursor[i] = r;
        }
        if (i == 0) g_rowstart[NN] = E;
    } else {
        // ---------------- node0 role: 64 nodes, 1024 threads = (node, feature) ----
        __shared__ float sx[64 * F_IN];
        __shared__ float sW1[F_IN * HID];
        __shared__ float sWc0[HID * HID];
        __shared__ float sh[64 * HID];
        __shared__ float sb1[HID];

        for (int i = tid; i < F_IN * HID; i += 1024) sW1[i] = W1[i];
        for (int i = tid; i < HID * HID; i += 1024) sWc0[i] = Wc0[i];
        if (tid < HID) sb1[tid] = b1[tid];

        int base = (blockIdx.x - SCAN_G) * 64;
        int nrows = NN - base; if (nrows > 64) nrows = 64;
        for (int i = tid; i < nrows * F_IN; i += 1024)
            sx[i] = x[(long long)base * F_IN + i];
        __syncthreads();

        int ln = tid >> 4, j = tid & 15;    // node 0..63, feature 0..15
        int node = base + ln;
        if (node < NN) {
            float acc = sb1[j];
            const float* xr = &sx[ln * F_IN];
#pragma unroll 4
            for (int k = 0; k < F_IN; k++)
                acc += xr[k] * sW1[k * HID + j];
            sh[ln * HID + j] = fmaxf(acc, 0.f);
        }
        __syncthreads();
        if (node < NN) {
            float t = 0.f;
            const float* hr = &sh[ln * HID];
#pragma unroll
            for (int i = 0; i < HID; i++)
                t += hr[i] * sWc0[i * HID + j];
            float dinv = rsqrtf((float)(g_deg[node] + 1));  // read-only here
            if (j == 0) g_dinv[node] = dinv;
            g_hs[node * HID + j] = dinv * t;
        }
    }
}

// ---------------------------------------------------------------------------
// K3: CSR fill — col[pos] = src, pos from per-dst cursor
__global__ void k_fill(const int* __restrict__ src, const int* __restrict__ dst, int E) {
    int t = blockIdx.x * blockDim.x + threadIdx.x;
    int e = t * 4;
    if (e + 3 < E) {
        int4 d = *(const int4*)(dst + e);
        int4 s = *(const int4*)(src + e);
        g_col[atomicAdd(&g_cursor[d.x], 1)] = s.x;
        g_col[atomicAdd(&g_cursor[d.y], 1)] = s.y;
        g_col[atomicAdd(&g_cursor[d.z], 1)] = s.z;
        g_col[atomicAdd(&g_cursor[d.w], 1)] = s.w;
    } else {
        for (int k = e; k < E; k++)
            g_col[atomicAdd(&g_cursor[dst[k]], 1)] = src[k];
    }
}

// ---------------------------------------------------------------------------
// Warp-collective CSR gather (R4's known-best 8-edge formulation).
__device__ __forceinline__ float warp_gather(const float* __restrict__ hs,
                                             int node, int lane) {
    int rs = g_rowstart[node];
    int re = g_rowstart[node + 1];
    int esub = lane >> 2, q = lane & 3;
    float4 acc = {0.f, 0.f, 0.f, 0.f};
    for (int b = rs; b < re; b += 8) {
        int c = 0;
        int le = b + (lane & 7);
        if (lane < 8 && le < re) c = g_col[le];
        int s = __shfl_sync(0xffffffff, c, esub);
        if (b + esub < re) {
            float4 v = *(const float4*)&hs[s * HID + q * 4];
            acc.x += v.x; acc.y += v.y; acc.z += v.z; acc.w += v.w;
        }
    }
#pragma unroll
    for (int off = 4; off < 32; off <<= 1) {
        acc.x += __shfl_xor_sync(0xffffffff, acc.x, off);
        acc.y += __shfl_xor_sync(0xffffffff, acc.y, off);
        acc.z += __shfl_xor_sync(0xffffffff, acc.z, off);
        acc.w += __shfl_xor_sync(0xffffffff, acc.w, off);
    }
    int q2 = lane >> 2, c2 = lane & 3;
    float ax = __shfl_sync(0xffffffff, acc.x, q2);
    float ay = __shfl_sync(0xffffffff, acc.y, q2);
    float az = __shfl_sync(0xffffffff, acc.z, q2);
    float aw = __shfl_sync(0xffffffff, acc.w, q2);
    return (c2 == 0) ? ax : (c2 == 1) ? ay : (c2 == 2) ? az : aw;
}

// ---------------------------------------------------------------------------
// K4: conv1 aggregate + relu + @Wc1 + dinv, fused. Warp per node. hs -> hs2.
// Also zeroes g_deg (restores call-entry invariant; safe: all deg readers done).
__global__ void k_gather_mid(const float* __restrict__ bc,
                             const float* __restrict__ Wnext) {
    __shared__ float sW[HID * HID + 32];   // padded: lanes>=16 dead-read up to [271]
    __shared__ float sb[HID];
    int tid = threadIdx.x;
    for (int i = tid; i < HID * HID; i += 256) sW[i] = Wnext[i];
    for (int i = tid + HID * HID; i < HID * HID + 32; i += 256) sW[i] = 0.f;
    if (tid < HID) sb[tid] = bc[tid];
    __syncthreads();

    int warp = tid >> 5, lane = tid & 31;
    int node = blockIdx.x * 8 + warp;     // NN % 8 == 0

    if (lane == 0) g_deg[node] = 0;       // restore invariant for next call

    float agg = warp_gather(g_hs, node, lane);
    float dinv = g_dinv[node];
    float h = 0.f;
    if (lane < HID)
        h = fmaxf(dinv * (agg + g_hs[node * HID + lane]) + sb[lane], 0.f);

    float t = 0.f;
#pragma unroll
    for (int i = 0; i < HID; i++) {
        float hi = __shfl_sync(0xffffffff, h, i);
        t += hi * sW[i * HID + lane];     // lanes>=16 read padded zeros, discarded
    }
    if (lane < HID) g_hs2[node * HID + lane] = dinv * t;
}

// ---------------------------------------------------------------------------
// K5: conv2 aggregate + relu + @W2 + b2 + log_softmax. Warp per node.
__global__ void k_gather_out(const float* __restrict__ bc1,
                             const float* __restrict__ W2,
                             const float* __restrict__ b2,
                             float* __restrict__ out) {
    __shared__ float sW2[HID * NC];        // 288 floats — strided staging loop!
    __shared__ float sb2[NC];
    __shared__ float sbc[HID];
    int tid = threadIdx.x;
    for (int i = tid; i < HID * NC; i += 256) sW2[i] = W2[i];
    if (tid < NC) sb2[tid] = b2[tid];
    if (tid < HID) sbc[tid] = bc1[tid];
    __syncthreads();

    int warp = tid >> 5, lane = tid & 31;
    int node = blockIdx.x * 8 + warp;

    float agg = warp_gather(g_hs2, node, lane);
    float dinv = g_dinv[node];
    float h = 0.f;
    if (lane < HID)
        h = fmaxf(dinv * (agg + g_hs2[node * HID + lane]) + sbc[lane], 0.f);

    float o = (lane < NC) ? sb2[lane] : -1e30f;
#pragma unroll
    for (int i = 0; i < HID; i++) {
        float hi = __shfl_sync(0xffffffff, h, i);
        if (lane < NC) o += hi * sW2[i * NC + lane];
    }
    float m = o;
#pragma unroll
    for (int off = 16; off; off >>= 1) m = fmaxf(m, __shfl_xor_sync(0xffffffff, m, off));
    float ex = (lane < NC) ? __expf(o - m) : 0.f;
    float s = ex;
#pragma unroll
    for (int off = 16; off; off >>= 1) s += __shfl_xor_sync(0xffffffff, s, off);
    float ls = m + __logf(s);
    if (lane < NC) out[node * NC + lane] = o - ls;
}

// ---------------------------------------------------------------------------
extern "C" void kernel_launch(void* const* d_in, const int* in_sizes, int n_in,
                              void* d_out, int out_size) {
    const float* x   = (const float*)d_in[0];
    const int*   ei  = (const int*)d_in[1];     // int32 indices
    const float* W1  = (const float*)d_in[2];
    const float* b1  = (const float*)d_in[3];
    const float* Wc0 = (const float*)d_in[4];
    const float* bc0 = (const float*)d_in[5];
    const float* Wc1 = (const float*)d_in[6];
    const float* bc1 = (const float*)d_in[7];
    const float* W2  = (const float*)d_in[8];
    const float* b2  = (const float*)d_in[9];
    float* out = (float*)d_out;

    int E = in_sizes[1] / 2;            // 3200000
    const int* src = ei;
    const int* dst = ei + E;

    int eb4 = (E / 4 + 255) / 256;      // edge blocks, 4 edges/thread
    int n0_blocks = (NN + 63) / 64;     // 1563

    k_deg<<<eb4, 256>>>(dst, E);                               // 1
    k_scan_node0<<<SCAN_G + n0_blocks, 1024>>>(x, W1, b1, Wc0, E); // 2
    k_fill<<<eb4, 256>>>(src, dst, E);                         // 3
    k_gather_mid<<<NN / 8, 256>>>(bc0, Wc1);                   // 4 <- profiled
    k_gather_out<<<NN / 8, 256>>>(bc1, W2, b2, out);           // 5
}

// round 10
// speedup vs baseline: 1.1491x; 1.1491x over previous
#include <cuda_runtime.h>

#define NN 100000
#define EE 3200000
#define F_IN 100
#define HID 16
#define NC 18

// Scratch (static device arrays — zero-initialized at module load)
__device__ __align__(128) float g_hs[NN * HID];    // dinv*[h@W] per node (conv input msg)
__device__ __align__(128) float g_hs2[NN * HID];   // double buffer for conv2
__device__ __align__(128) float g_dinv[NN];
__device__ __align__(128) int   g_deg[NN];         // INVARIANT: zero at call entry
__device__ __align__(128) int   g_rowstart[NN + 1];
__device__ __align__(128) int   g_cursor[NN];
__device__ __align__(128) int   g_col[EE];         // CSR (by dst) column = src
__device__ __align__(128) int   g_btot[128];

#define SCAN_B 1024
#define SCAN_G 98   // 98*1024 = 100352 >= NN

// ---------------------------------------------------------------------------
// K1: in-degree count (int4-vectorized index loads). g_deg is zero on entry.
__global__ void k_deg(const int* __restrict__ dst, int E) {
    int t = blockIdx.x * blockDim.x + threadIdx.x;
    int e = t * 4;
    if (e + 3 < E) {
        int4 d = *(const int4*)(dst + e);
        atomicAdd(&g_deg[d.x], 1);
        atomicAdd(&g_deg[d.y], 1);
        atomicAdd(&g_deg[d.z], 1);
        atomicAdd(&g_deg[d.w], 1);
    } else {
        for (int k = e; k < E; k++) atomicAdd(&g_deg[dst[k]], 1);
    }
}

// ---------------------------------------------------------------------------
// K2: per-block exclusive scan of deg -> rowstart (local), block totals out.
__global__ void k_scanA() {
    __shared__ int s[SCAN_B];
    int i = blockIdx.x * SCAN_B + threadIdx.x;
    int v = (i < NN) ? g_deg[i] : 0;
    s[threadIdx.x] = v;
    __syncthreads();
    for (int off = 1; off < SCAN_B; off <<= 1) {
        int t = (threadIdx.x >= off) ? s[threadIdx.x - off] : 0;
        __syncthreads();
        s[threadIdx.x] += t;
        __syncthreads();
    }
    if (i < NN) g_rowstart[i] = s[threadIdx.x] - v;     // exclusive within block
    if (threadIdx.x == SCAN_B - 1) g_btot[blockIdx.x] = s[threadIdx.x];
}

// K3 (merged scanB+scanC): every block redundantly scans the 98 block totals
// in smem (cheap), then applies its own exclusive offset to rowstart+cursor.
__global__ void k_scanBC(int E) {
    __shared__ int s[128];
    int tid = threadIdx.x;
    if (tid < 128) s[tid] = (tid < SCAN_G) ? g_btot[tid] : 0;
    __syncthreads();
    for (int off = 1; off < 128; off <<= 1) {
        int t = 0;
        if (tid < 128 && tid >= off) t = s[tid - off];
        __syncthreads();
        if (tid < 128) s[tid] += t;
        __syncthreads();
    }
    int boff = (blockIdx.x == 0) ? 0 : s[blockIdx.x - 1];  // excl. offset of this block
    int i = blockIdx.x * SCAN_B + tid;
    if (i < NN) {
        int r = g_rowstart[i] + boff;
        g_rowstart[i] = r;
        g_cursor[i] = r;
    }
    if (i == 0) g_rowstart[NN] = E;
}

// ---------------------------------------------------------------------------
// K4: CSR fill — col[pos] = src, pos from per-dst cursor
__global__ void k_fill(const int* __restrict__ src, const int* __restrict__ dst, int E) {
    int t = blockIdx.x * blockDim.x + threadIdx.x;
    int e = t * 4;
    if (e + 3 < E) {
        int4 d = *(const int4*)(dst + e);
        int4 s = *(const int4*)(src + e);
        g_col[atomicAdd(&g_cursor[d.x], 1)] = s.x;
        g_col[atomicAdd(&g_cursor[d.y], 1)] = s.y;
        g_col[atomicAdd(&g_cursor[d.z], 1)] = s.z;
        g_col[atomicAdd(&g_cursor[d.w], 1)] = s.w;
    } else {
        for (int k = e; k < E; k++)
            g_col[atomicAdd(&g_cursor[dst[k]], 1)] = src[k];
    }
}

// ---------------------------------------------------------------------------
// K5: h0 = relu(x@W1+b1); hs = dinv * (h0@Wc0). 64 nodes/block, 256 threads.
// Re-zeroes g_deg (restores invariant) — deg read uniformly BEFORE zeroing.
__global__ void k_node0(const float* __restrict__ x,
                        const float* __restrict__ W1,
                        const float* __restrict__ b1,
                        const float* __restrict__ Wc0) {
    __shared__ __align__(16) float sx[64 * F_IN];          // 25.6 KB
    __shared__ __align__(16) float sW1[F_IN * HID];        // 6.4 KB
    __shared__ __align__(16) float sWc0[HID * HID];
    __shared__ __align__(16) float sh[64 * HID];
    __shared__ __align__(16) float sb1[HID];

    int tid = threadIdx.x;
    for (int i = tid; i < F_IN * HID; i += 256) sW1[i] = W1[i];
    for (int i = tid; i < HID * HID; i += 256) sWc0[i] = Wc0[i];
    if (tid < HID) sb1[tid] = b1[tid];

    int base = blockIdx.x * 64;
    int nrows = NN - base; if (nrows > 64) nrows = 64;
    for (int i = tid; i < nrows * F_IN; i += 256)
        sx[i] = x[(long long)base * F_IN + i];
    __syncthreads();

    int ln = tid >> 2, jq = tid & 3;
    int node = base + ln;
    bool valid = (node < NN);

    if (valid) {
        float4 a = *(const float4*)&sb1[jq * 4];
        const float* xr = &sx[ln * F_IN];
#pragma unroll 4
        for (int k = 0; k < F_IN; k++) {
            float xv = xr[k];
            float4 w = *(const float4*)&sW1[k * HID + jq * 4];
            a.x += xv * w.x; a.y += xv * w.y; a.z += xv * w.z; a.w += xv * w.w;
        }
        a.x = fmaxf(a.x, 0.f); a.y = fmaxf(a.y, 0.f);
        a.z = fmaxf(a.z, 0.f); a.w = fmaxf(a.w, 0.f);
        *(float4*)&sh[ln * HID + jq * 4] = a;
    }
    __syncthreads();

    // Uniform deg read for all 4 threads of the node BEFORE anyone zeroes it.
    int d = valid ? g_deg[node] : 0;
    float dinv = rsqrtf((float)(d + 1));
    __syncwarp();
    if (valid && jq == 0) {
        g_dinv[node] = dinv;
        g_deg[node] = 0;                 // restore invariant for next call
    }

    if (valid) {
        float4 t = {0.f, 0.f, 0.f, 0.f};
        const float* hr = &sh[ln * HID];
#pragma unroll
        for (int i = 0; i < HID; i++) {
            float hv = hr[i];
            float4 w = *(const float4*)&sWc0[i * HID + jq * 4];
            t.x += hv * w.x; t.y += hv * w.y; t.z += hv * w.z; t.w += hv * w.w;
        }
        float4 o = {dinv * t.x, dinv * t.y, dinv * t.z, dinv * t.w};
        *(float4*)&g_hs[node * HID + jq * 4] = o;
    }
}

// ---------------------------------------------------------------------------
// Warp-collective CSR gather — instruction-lean version.
// No shuffle in the loop: each lane loads its OWN col index (8 distinct
// addresses x4 redundant lanes = 1 coalesced wavefront). Main loop is
// predicate-free, unrolled 2x (16 edges/trip); 8-edge predicated remainder.
// Lane (esub=lane>>2, q=lane&3) accumulates feature-quad q of edge-slot esub.
__device__ __forceinline__ float warp_gather(const float* __restrict__ hs,
                                             int node, int lane) {
    int rs = g_rowstart[node];
    int re = g_rowstart[node + 1];
    int esub = lane >> 2, q = lane & 3;
    const float* hsq = hs + q * 4;        // per-lane feature-quad base
    float4 acc = {0.f, 0.f, 0.f, 0.f};

    int b = rs;
    for (; b + 16 <= re; b += 16) {       // predicate-free main loop
        int c0 = g_col[b + esub];
        int c1 = g_col[b + 8 + esub];
        float4 v0 = *(const float4*)&hsq[c0 * HID];
        float4 v1 = *(const float4*)&hsq[c1 * HID];
        acc.x += v0.x + v1.x;
        acc.y += v0.y + v1.y;
        acc.z += v0.z + v1.z;
        acc.w += v0.w + v1.w;
    }
    for (; b < re; b += 8) {              // remainder, predicated
        int le = b + esub;
        if (le < re) {
            int c = g_col[le];
            float4 v = *(const float4*)&hsq[c * HID];
            acc.x += v.x; acc.y += v.y; acc.z += v.z; acc.w += v.w;
        }
    }

    // Reduce over edge-slots (xor 4,8,16 preserves q).
#pragma unroll
    for (int off = 4; off < 32; off <<= 1) {
        acc.x += __shfl_xor_sync(0xffffffff, acc.x, off);
        acc.y += __shfl_xor_sync(0xffffffff, acc.y, off);
        acc.z += __shfl_xor_sync(0xffffffff, acc.z, off);
        acc.w += __shfl_xor_sync(0xffffffff, acc.w, off);
    }
    // Redistribute: lane f wants component (f&3) of quad (f>>2)'s sum.
    int q2 = lane >> 2, c2 = lane & 3;
    float ax = __shfl_sync(0xffffffff, acc.x, q2);
    float ay = __shfl_sync(0xffffffff, acc.y, q2);
    float az = __shfl_sync(0xffffffff, acc.z, q2);
    float aw = __shfl_sync(0xffffffff, acc.w, q2);
    return (c2 == 0) ? ax : (c2 == 1) ? ay : (c2 == 2) ? az : aw;
}

// ---------------------------------------------------------------------------
// K6: conv1 aggregate + relu + @Wc1 + dinv, fused. Warp per node. hs -> hs2.
__global__ void k_gather_mid(const float* __restrict__ bc,
                             const float* __restrict__ Wnext) {
    __shared__ float sW[HID * HID + 32];   // padded: lanes>=16 dead-read up to [271]
    __shared__ float sb[HID];
    int tid = threadIdx.x;
    for (int i = tid; i < HID * HID; i += 256) sW[i] = Wnext[i];
    for (int i = tid + HID * HID; i < HID * HID + 32; i += 256) sW[i] = 0.f;
    if (tid < HID) sb[tid] = bc[tid];
    __syncthreads();

    int warp = tid >> 5, lane = tid & 31;
    int node = blockIdx.x * 8 + warp;     // NN % 8 == 0

    float agg = warp_gather(g_hs, node, lane);
    float dinv = g_dinv[node];
    float h = 0.f;
    if (lane < HID)
        h = fmaxf(dinv * (agg + g_hs[node * HID + lane]) + sb[lane], 0.f);

    float t = 0.f;
#pragma unroll
    for (int i = 0; i < HID; i++) {
        float hi = __shfl_sync(0xffffffff, h, i);
        t += hi * sW[i * HID + lane];     // lanes>=16 read padded zeros, discarded
    }
    if (lane < HID) g_hs2[node * HID + lane] = dinv * t;
}

// ---------------------------------------------------------------------------
// K7: conv2 aggregate + relu + @W2 + b2 + log_softmax. Warp per node.
__global__ void k_gather_out(const float* __restrict__ bc1,
                             const float* __restrict__ W2,
                             const float* __restrict__ b2,
                             float* __restrict__ out) {
    __shared__ float sW2[HID * NC];        // 288 floats — strided staging loop!
    __shared__ float sb2[NC];
    __shared__ float sbc[HID];
    int tid = threadIdx.x;
    for (int i = tid; i < HID * NC; i += 256) sW2[i] = W2[i];
    if (tid < NC) sb2[tid] = b2[tid];
    if (tid < HID) sbc[tid] = bc1[tid];
    __syncthreads();

    int warp = tid >> 5, lane = tid & 31;
    int node = blockIdx.x * 8 + warp;

    float agg = warp_gather(g_hs2, node, lane);
    float dinv = g_dinv[node];
    float h = 0.f;
    if (lane < HID)
        h = fmaxf(dinv * (agg + g_hs2[node * HID + lane]) + sbc[lane], 0.f);

    float o = (lane < NC) ? sb2[lane] : -1e30f;
#pragma unroll
    for (int i = 0; i < HID; i++) {
        float hi = __shfl_sync(0xffffffff, h, i);
        if (lane < NC) o += hi * sW2[i * NC + lane];
    }
    float m = o;
#pragma unroll
    for (int off = 16; off; off >>= 1) m = fmaxf(m, __shfl_xor_sync(0xffffffff, m, off));
    float ex = (lane < NC) ? __expf(o - m) : 0.f;
    float s = ex;
#pragma unroll
    for (int off = 16; off; off >>= 1) s += __shfl_xor_sync(0xffffffff, s, off);
    float ls = m + __logf(s);
    if (lane < NC) out[node * NC + lane] = o - ls;
}

// ---------------------------------------------------------------------------
extern "C" void kernel_launch(void* const* d_in, const int* in_sizes, int n_in,
                              void* d_out, int out_size) {
    const float* x   = (const float*)d_in[0];
    const int*   ei  = (const int*)d_in[1];     // int32 indices
    const float* W1  = (const float*)d_in[2];
    const float* b1  = (const float*)d_in[3];
    const float* Wc0 = (const float*)d_in[4];
    const float* bc0 = (const float*)d_in[5];
    const float* Wc1 = (const float*)d_in[6];
    const float* bc1 = (const float*)d_in[7];
    const float* W2  = (const float*)d_in[8];
    const float* b2  = (const float*)d_in[9];
    float* out = (float*)d_out;

    int E = in_sizes[1] / 2;            // 3200000
    const int* src = ei;
    const int* dst = ei + E;

    int eb4 = (E / 4 + 255) / 256;      // edge blocks, 4 edges/thread

    k_deg<<<eb4, 256>>>(dst, E);                        // 1
    k_scanA<<<SCAN_G, SCAN_B>>>();                      // 2
    k_scanBC<<<SCAN_G, SCAN_B>>>(E);                    // 3
    k_fill<<<eb4, 256>>>(src, dst, E);                  // 4
    k_node0<<<(NN + 63) / 64, 256>>>(x, W1, b1, Wc0);   // 5
    k_gather_mid<<<NN / 8, 256>>>(bc0, Wc1);            // 6
    k_gather_out<<<NN / 8, 256>>>(bc1, W2, b2, out);    // 7
}